// round 12
// baseline (speedup 1.0000x reference)
#include <cuda_runtime.h>

// GRITAttention — counting sort, unfused accum + persistent double-buffered GEMM.
// R11: k_out v4 — 148 blocks x 512 threads, full W in smem (96KB), sA double
// buffer filled by cp.async; 4 warps/SMSP; FMA-pipe-bound.

#define DM 128
#define DE 64
#define MAX_NODES 200000
#define MAX_E     600000

typedef unsigned long long ull;

// ---------------- device scratch (no allocation allowed) ----------------
__device__ __align__(16) float g_wqa[DM];
__device__ __align__(16) float g_wka[DM];
__device__ __align__(16) float g_wewa[DE];
__device__ float g_cbias;
__device__ int   g_is64;

__device__ __align__(16) float g_qa[MAX_NODES];
__device__ __align__(16) float g_ka[MAX_NODES];
__device__ __align__(16) float g_attsum[MAX_NODES];
__device__ __align__(16) float g_alphasum[MAX_NODES];
__device__ __align__(16) float g_attexp[MAX_E];
__device__ __align__(16) float g_accx[(size_t)MAX_NODES * DM];
__device__ __align__(16) float g_acc64[(size_t)MAX_NODES * DE];

// sort structures
__device__ __align__(16) int  g_hist[MAX_NODES];
__device__ __align__(16) int  g_segstart[MAX_NODES];
__device__ __align__(16) int  g_cursor[MAX_NODES];
__device__ __align__(16) int  g_blocksum[1024];
__device__ __align__(16) int2 g_epair[MAX_E];          // {gsrc, gdst} cached by edge1
__device__ __align__(16) int4 g_sp[MAX_E];             // {gdst, e, alpha(bits), pad}

// ---------------- helpers ----------------
__device__ __forceinline__ void ffma2(ull& d, ull a, ull b) {
    asm("fma.rn.f32x2 %0, %1, %2, %3;" : "=l"(d) : "l"(a), "l"(b), "l"(d));
}
__device__ __forceinline__ float hadd2(ull v) {
    float lo = __uint_as_float((unsigned)(v & 0xffffffffull));
    float hi = __uint_as_float((unsigned)(v >> 32));
    return lo + hi;
}
__device__ __forceinline__ int ld_idx(const void* p, long long i, int is64) {
    if (is64) return (int)((const long long*)p)[i];
    return ((const int*)p)[i];
}
__device__ __forceinline__ unsigned smem_u32(const void* p) {
    return (unsigned)__cvta_generic_to_shared(p);
}

// ---------------- kernels ----------------

// merged: zero (blocks 0..gridDim-2) + prep + dtype-detect (last block)
__global__ void k_init(const float* __restrict__ Wq, const float* __restrict__ bq,
                       const float* __restrict__ Wk, const float* __restrict__ bk,
                       const float* __restrict__ Wew, const float* __restrict__ bew,
                       const float* __restrict__ Wa, const int* __restrict__ ei,
                       int nodes) {
    if (blockIdx.x == gridDim.x - 1) {
        int t = threadIdx.x;
        if (t < DM) {
            float s1 = 0.f, s2 = 0.f;
            for (int j = 0; j < DM; j++) {
                float w = Wa[j];
                s1 += Wq[t * DM + j] * w;
                s2 += Wk[t * DM + j] * w;
            }
            g_wqa[t] = s1;
            g_wka[t] = s2;
        } else if (t < DM + DE) {
            int r = t - DM;
            float s = 0.f;
            for (int c = 0; c < DM; c++) s += Wew[r * DM + c] * Wa[c];
            g_wewa[r] = s;
        } else if (t == DM + DE) {
            float s = 0.f;
            for (int j = 0; j < DM; j++) s += (bq[j] + bk[j] + bew[j]) * Wa[j];
            g_cbias = s;
        } else if (t == DM + DE + 1) {
            g_is64 = ((ei[1] | ei[3] | ei[5] | ei[7]) == 0) ? 1 : 0;
        }
    } else {
        int i = blockIdx.x * blockDim.x + threadIdx.x;
        int stride = (gridDim.x - 1) * blockDim.x;
        for (int j = i; j < nodes; j += stride) { g_attsum[j] = 0.f; g_hist[j] = 0; }
    }
}

// per-node scalars qa = x·wqa, ka = x·wka  (one warp per FOUR nodes -> MLP 4)
__global__ void k_qaka(const float* __restrict__ x, int nodes) {
    int w = (blockIdx.x * blockDim.x + threadIdx.x) >> 5;
    int lane = threadIdx.x & 31;
    int g0 = w * 4;
    if (g0 >= nodes) return;
    const float4* x4 = (const float4*)x;
    float4 wq = ((const float4*)g_wqa)[lane];
    float4 wk = ((const float4*)g_wka)[lane];
    float pq[4], pk[4];
    float4 a[4];
    #pragma unroll
    for (int j = 0; j < 4; j++) {
        int gi = (g0 + j < nodes) ? g0 + j : g0;
        a[j] = x4[(size_t)gi * 32 + lane];
    }
    #pragma unroll
    for (int j = 0; j < 4; j++) {
        pq[j] = a[j].x * wq.x + a[j].y * wq.y + a[j].z * wq.z + a[j].w * wq.w;
        pk[j] = a[j].x * wk.x + a[j].y * wk.y + a[j].z * wk.z + a[j].w * wk.w;
    }
    #pragma unroll
    for (int off = 16; off; off >>= 1) {
        #pragma unroll
        for (int j = 0; j < 4; j++) {
            pq[j] += __shfl_down_sync(0xffffffffu, pq[j], off);
            pk[j] += __shfl_down_sync(0xffffffffu, pk[j], off);
        }
    }
    if (lane == 0) {
        #pragma unroll
        for (int j = 0; j < 4; j++) {
            if (g0 + j < nodes) { g_qa[g0 + j] = pq[j]; g_ka[g0 + j] = pk[j]; }
        }
    }
}

// pass 1: per edge logit -> exp, denominator per gdst, histogram per gsrc,
// cache (gsrc,gdst). 8 lanes/edge.
__global__ void k_edge1(const void* __restrict__ ei, const float* __restrict__ emb,
                        const void* __restrict__ bi, int E, int Nn) {
    int gid = blockIdx.x * blockDim.x + threadIdx.x;
    int e = gid >> 3;
    int l = gid & 7;
    bool valid = e < E;
    int ec = valid ? e : 0;
    const float4* e4 = (const float4*)emb;
    float4 a = e4[(size_t)ec * 16 + l * 2];
    float4 b = e4[(size_t)ec * 16 + l * 2 + 1];
    float4 w1 = ((const float4*)g_wewa)[l * 2];
    float4 w2 = ((const float4*)g_wewa)[l * 2 + 1];
    float p = a.x * w1.x + a.y * w1.y + a.z * w1.z + a.w * w1.w
            + b.x * w2.x + b.y * w2.y + b.z * w2.z + b.w * w2.w;
    p += __shfl_down_sync(0xffffffffu, p, 4, 8);
    p += __shfl_down_sync(0xffffffffu, p, 2, 8);
    p += __shfl_down_sync(0xffffffffu, p, 1, 8);
    if (valid && l == 0) {
        int is64 = g_is64;
        int s  = ld_idx(ei, e, is64);
        int d  = ld_idx(ei, (long long)E + e, is64);
        int bb = ld_idx(bi, e, is64);
        int gsrc = bb * Nn + s;
        int gdst = bb * Nn + d;
        g_epair[e] = make_int2(gsrc, gdst);
        float logit = (g_qa[gsrc] + g_ka[gdst] + p + g_cbias) * 0.25f; // 1/sqrt(16)
        float ex = expf(logit);
        g_attexp[e] = ex;
        atomicAdd(&g_attsum[gdst], ex);
        atomicAdd(&g_hist[gsrc], 1);
    }
}

// ---- 3-step exclusive scan of g_hist ----
__global__ void k_scan1(int nodes) {
    __shared__ int s[256];
    int i = blockIdx.x * 256 + threadIdx.x;
    int v = (i < nodes) ? g_hist[i] : 0;
    s[threadIdx.x] = v;
    __syncthreads();
    #pragma unroll
    for (int off = 128; off; off >>= 1) {
        if (threadIdx.x < off) s[threadIdx.x] += s[threadIdx.x + off];
        __syncthreads();
    }
    if (threadIdx.x == 0) g_blocksum[blockIdx.x] = s[0];
}

__global__ void k_scan2(int nb) {
    __shared__ int s[1024];
    int t = threadIdx.x;
    int v = (t < nb) ? g_blocksum[t] : 0;
    s[t] = v;
    __syncthreads();
    #pragma unroll
    for (int off = 1; off < 1024; off <<= 1) {
        int add = (t >= off) ? s[t - off] : 0;
        __syncthreads();
        s[t] += add;
        __syncthreads();
    }
    if (t < nb) g_blocksum[t] = s[t] - v;   // exclusive
}

__global__ void k_scan3(int nodes) {
    __shared__ int s[256];
    int i = blockIdx.x * 256 + threadIdx.x;
    int v = (i < nodes) ? g_hist[i] : 0;
    s[threadIdx.x] = v;
    __syncthreads();
    #pragma unroll
    for (int off = 1; off < 256; off <<= 1) {
        int add = (threadIdx.x >= off) ? s[threadIdx.x - off] : 0;
        __syncthreads();
        s[threadIdx.x] += add;
        __syncthreads();
    }
    if (i < nodes) {
        int start = g_blocksum[blockIdx.x] + s[threadIdx.x] - v;
        g_segstart[i] = start;
        g_cursor[i]   = start;
    }
}

// scatter: per edge, compute alpha, place packed payload into gsrc-sorted slot
__global__ void k_scatter(int E) {
    int e = blockIdx.x * blockDim.x + threadIdx.x;
    if (e >= E) return;
    int2 pr = g_epair[e];
    float alpha = g_attexp[e] / (g_attsum[pr.y] + 1e-9f);
    int pos = atomicAdd(&g_cursor[pr.x], 1);
    g_sp[pos] = make_int4(pr.y, e, __float_as_int(alpha), 0);
}

// segmented accumulation: one warp per node, registers only, 4-wide MLP
__global__ void k_accum(const float* __restrict__ x, const float* __restrict__ emb,
                        int nodes) {
    int g = (blockIdx.x * blockDim.x + threadIdx.x) >> 5;
    int lane = threadIdx.x & 31;
    if (g >= nodes) return;
    int i   = g_segstart[g];
    int end = g_cursor[g];
    const float4* x4 = (const float4*)x;
    const float2* e2 = (const float2*)emb;
    float4 ax = make_float4(0.f, 0.f, 0.f, 0.f);
    float2 ae = make_float2(0.f, 0.f);
    float asum = 0.f;
    for (; i + 3 < end; i += 4) {
        int4 p0 = __ldg(&g_sp[i]);
        int4 p1 = __ldg(&g_sp[i + 1]);
        int4 p2 = __ldg(&g_sp[i + 2]);
        int4 p3 = __ldg(&g_sp[i + 3]);
        float a0 = __int_as_float(p0.z), a1 = __int_as_float(p1.z);
        float a2 = __int_as_float(p2.z), a3 = __int_as_float(p3.z);
        float4 xv0 = x4[(size_t)p0.x * 32 + lane];
        float4 xv1 = x4[(size_t)p1.x * 32 + lane];
        float4 xv2 = x4[(size_t)p2.x * 32 + lane];
        float4 xv3 = x4[(size_t)p3.x * 32 + lane];
        float2 ev0 = e2[(size_t)p0.y * 32 + lane];
        float2 ev1 = e2[(size_t)p1.y * 32 + lane];
        float2 ev2 = e2[(size_t)p2.y * 32 + lane];
        float2 ev3 = e2[(size_t)p3.y * 32 + lane];
        ax.x += a0 * xv0.x + a1 * xv1.x + a2 * xv2.x + a3 * xv3.x;
        ax.y += a0 * xv0.y + a1 * xv1.y + a2 * xv2.y + a3 * xv3.y;
        ax.z += a0 * xv0.z + a1 * xv1.z + a2 * xv2.z + a3 * xv3.z;
        ax.w += a0 * xv0.w + a1 * xv1.w + a2 * xv2.w + a3 * xv3.w;
        ae.x += a0 * ev0.x + a1 * ev1.x + a2 * ev2.x + a3 * ev3.x;
        ae.y += a0 * ev0.y + a1 * ev1.y + a2 * ev2.y + a3 * ev3.y;
        asum += (a0 + a1) + (a2 + a3);
    }
    for (; i + 1 < end; i += 2) {
        int4 p0 = __ldg(&g_sp[i]);
        int4 p1 = __ldg(&g_sp[i + 1]);
        float a0 = __int_as_float(p0.z), a1 = __int_as_float(p1.z);
        float4 xv0 = x4[(size_t)p0.x * 32 + lane];
        float4 xv1 = x4[(size_t)p1.x * 32 + lane];
        float2 ev0 = e2[(size_t)p0.y * 32 + lane];
        float2 ev1 = e2[(size_t)p1.y * 32 + lane];
        ax.x += a0 * xv0.x + a1 * xv1.x;
        ax.y += a0 * xv0.y + a1 * xv1.y;
        ax.z += a0 * xv0.z + a1 * xv1.z;
        ax.w += a0 * xv0.w + a1 * xv1.w;
        ae.x += a0 * ev0.x + a1 * ev1.x;
        ae.y += a0 * ev0.y + a1 * ev1.y;
        asum += a0 + a1;
    }
    if (i < end) {
        int4 p = __ldg(&g_sp[i]);
        float a = __int_as_float(p.z);
        float4 xv = x4[(size_t)p.x * 32 + lane];
        float2 ev = e2[(size_t)p.y * 32 + lane];
        ax.x += a * xv.x; ax.y += a * xv.y; ax.z += a * xv.z; ax.w += a * xv.w;
        ae.x += a * ev.x; ae.y += a * ev.y;
        asum += a;
    }
    ((float4*)g_accx)[(size_t)g * 32 + lane] = ax;
    ((float2*)g_acc64)[(size_t)g * 32 + lane] = ae;
    if (lane == 0) g_alphasum[g] = asum;
}

// PERSISTENT GEMM v4: 148 blocks x 512 threads. Full W (192x128) in smem,
// double-buffered 32-row sA tiles filled by cp.async. Per-thread 2 rows x 4 cols.
#define SW_K2 96                       // 192/2 pair-rows
#define SA_STRIDE 196                  // floats per sA row (192 + 4 pad)
#define SA_FLOATS (32 * SA_STRIDE)     // 6272 floats per buffer
#define KOUT_BLOCKS 148

__global__ void __launch_bounds__(512, 1)
k_out(const float* __restrict__ Wv, const float* __restrict__ bv,
      const float* __restrict__ Wev, const float* __restrict__ bev,
      float* __restrict__ out, int nodes) {
    extern __shared__ float smem[];
    float* sW  = smem;                     // [96][256] pair-interleaved
    float* sAb = smem + SW_K2 * 256;       // two buffers of SA_FLOATS

    int tid = threadIdx.x;
    int tx  = tid & 31;      // cols tx*4 .. tx*4+3
    int wid = tid >> 5;      // 0..15 -> rows wid*2, wid*2+1

    // ---- load full W once: 6144 float4, 12 per thread ----
    #pragma unroll
    for (int t = 0; t < 12; t++) {
        int i4 = tid + t * 512;          // 0..6143
        int k  = i4 >> 5;                // 0..191
        int c4 = (i4 & 31) << 2;
        float4 v = (k < 128) ? *(const float4*)&Wv[k * DM + c4]
                             : *(const float4*)&Wev[(k - 128) * DM + c4];
        float* dst = &sW[(k >> 1) * 256 + (k & 1)];
        dst[(c4 + 0) * 2] = v.x;
        dst[(c4 + 1) * 2] = v.y;
        dst[(c4 + 2) * 2] = v.z;
        dst[(c4 + 3) * 2] = v.w;
    }

    float4 b1 = *(const float4*)&bv[tx * 4];
    float4 b2 = *(const float4*)&bev[tx * 4];
    float4 bs = make_float4(b1.x + b2.x, b1.y + b2.y, b1.z + b2.z, b1.w + b2.w);

    int ntiles = (nodes + 31) >> 5;

    // prologue: async-fill buffer 0 with this block's first tile
    int tile = blockIdx.x;
    if (tile < ntiles) {
        int g0 = tile << 5;
        #pragma unroll
        for (int t = 0; t < 3; t++) {
            int i4 = tid + t * 512;      // 0..1535
            int m  = i4 / 48;
            int kq = (i4 % 48) << 2;
            int gm = g0 + m; if (gm >= nodes) gm = nodes - 1;
            const float* src = (kq < 128)
                ? &g_accx[(size_t)gm * DM + kq]
                : &g_acc64[(size_t)gm * DE + (kq - 128)];
            unsigned s = smem_u32(&sAb[m * SA_STRIDE + kq]);
            asm volatile("cp.async.cg.shared.global [%0], [%1], 16;" :: "r"(s), "l"(src));
        }
        asm volatile("cp.async.commit_group;" ::: "memory");
    }

    int cur = 0;
    for (; tile < ntiles; tile += KOUT_BLOCKS) {
        float* bufc = sAb + cur * SA_FLOATS;
        asm volatile("cp.async.wait_group 0;" ::: "memory");
        __syncthreads();   // buf(cur) filled; W ready; prior compute on buf(cur^1) done

        int nt = tile + KOUT_BLOCKS;
        if (nt < ntiles) {   // prefetch next tile into the other buffer
            int g0n = nt << 5;
            float* bufn = sAb + (cur ^ 1) * SA_FLOATS;
            #pragma unroll
            for (int t = 0; t < 3; t++) {
                int i4 = tid + t * 512;
                int m  = i4 / 48;
                int kq = (i4 % 48) << 2;
                int gm = g0n + m; if (gm >= nodes) gm = nodes - 1;
                const float* src = (kq < 128)
                    ? &g_accx[(size_t)gm * DM + kq]
                    : &g_acc64[(size_t)gm * DE + (kq - 128)];
                unsigned s = smem_u32(&bufn[m * SA_STRIDE + kq]);
                asm volatile("cp.async.cg.shared.global [%0], [%1], 16;" :: "r"(s), "l"(src));
            }
            asm volatile("cp.async.commit_group;" ::: "memory");
        }

        // ---- compute: 96 k2 steps, 2 rows x 4 col-pairs per thread ----
        ull acc[2][4];
        #pragma unroll
        for (int i = 0; i < 2; i++)
            #pragma unroll
            for (int j = 0; j < 4; j++) acc[i][j] = 0ull;

        const float* r0 = &bufc[(wid * 2 + 0) * SA_STRIDE];
        const float* r1 = &bufc[(wid * 2 + 1) * SA_STRIDE];
        #pragma unroll 8
        for (int k2 = 0; k2 < SW_K2; k2++) {
            ull a0 = *(const ull*)&r0[k2 * 2];      // warp-uniform -> broadcast
            ull a1 = *(const ull*)&r1[k2 * 2];
            ulonglong2 p0 = *(const ulonglong2*)&sW[k2 * 256 + tx * 8];
            ulonglong2 p1 = *(const ulonglong2*)&sW[k2 * 256 + tx * 8 + 4];
            ffma2(acc[0][0], a0, p0.x);
            ffma2(acc[0][1], a0, p0.y);
            ffma2(acc[0][2], a0, p1.x);
            ffma2(acc[0][3], a0, p1.y);
            ffma2(acc[1][0], a1, p0.x);
            ffma2(acc[1][1], a1, p0.y);
            ffma2(acc[1][2], a1, p1.x);
            ffma2(acc[1][3], a1, p1.y);
        }

        // ---- epilogue ----
        int g0 = tile << 5;
        #pragma unroll
        for (int i = 0; i < 2; i++) {
            int g = g0 + wid * 2 + i;
            if (g < nodes) {
                float as = g_alphasum[g];
                float4 o;
                o.x = hadd2(acc[i][0]) + as * bs.x;
                o.y = hadd2(acc[i][1]) + as * bs.y;
                o.z = hadd2(acc[i][2]) + as * bs.z;
                o.w = hadd2(acc[i][3]) + as * bs.w;
                *(float4*)&out[(size_t)g * DM + tx * 4] = o;
            }
        }
        cur ^= 1;
    }
}

// ---------------- launcher ----------------
extern "C" void kernel_launch(void* const* d_in, const int* in_sizes, int n_in,
                              void* d_out, int out_size) {
    const float* x   = (const float*)d_in[0];
    const void*  ei  = d_in[1];
    const float* emb = (const float*)d_in[2];
    const void*  bi  = d_in[3];
    int base = 4;
    if (n_in >= 16 && in_sizes[4] <= 2) base = 5;
    const float* Wq  = (const float*)d_in[base + 0];
    const float* bq  = (const float*)d_in[base + 1];
    const float* Wk  = (const float*)d_in[base + 2];
    const float* bk  = (const float*)d_in[base + 3];
    const float* Wv  = (const float*)d_in[base + 4];
    const float* bv  = (const float*)d_in[base + 5];
    const float* Wew = (const float*)d_in[base + 6];
    const float* bew = (const float*)d_in[base + 7];
    const float* Wev = (const float*)d_in[base + 8];
    const float* bev = (const float*)d_in[base + 9];
    const float* Wa  = (const float*)d_in[base + 10];

    int nodes = in_sizes[0] / DM;   // B*N
    int E     = in_sizes[3];
    int Nn    = nodes / 4;          // N (B = 4)
    int nb    = (nodes + 255) / 256;

    // smem: 96*256 (sW) + 2*6272 (sA buffers) floats = 37120 floats = 148480 B
    int smem_bytes = (SW_K2 * 256 + 2 * SA_FLOATS) * (int)sizeof(float);
    cudaFuncSetAttribute(k_out, cudaFuncAttributeMaxDynamicSharedMemorySize, smem_bytes);

    k_init<<<257, 256>>>(Wq, bq, Wk, bk, Wew, bew, Wa, (const int*)ei, nodes);
    k_qaka<<<(nodes / 4 + 7) / 8, 256>>>(x, nodes);
    k_edge1<<<(E + 31) / 32, 256>>>(ei, emb, bi, E, Nn);
    k_scan1<<<nb, 256>>>(nodes);
    k_scan2<<<1, 1024>>>(nb);
    k_scan3<<<nb, 256>>>(nodes);
    k_scatter<<<(E + 255) / 256, 256>>>(E);
    k_accum<<<(nodes + 7) / 8, 256>>>(x, emb, nodes);
    k_out<<<KOUT_BLOCKS, 512, smem_bytes>>>(Wv, bv, Wev, bev, (float*)d_out, nodes);
}

// round 13
// speedup vs baseline: 1.6750x; 1.6750x over previous
#include <cuda_runtime.h>

// GRITAttention — counting sort, unfused accum + persistent conflict-free GEMM.
// R12: k_out v5 — full W in smem with XOR-swizzled conflict-free layout,
// k2-major pair-packed sA (LDS.128 broadcasts), BM=64, 256 thr, FMA-bound.

#define DM 128
#define DE 64
#define MAX_NODES 200000
#define MAX_E     600000

typedef unsigned long long ull;

// ---------------- device scratch (no allocation allowed) ----------------
__device__ __align__(16) float g_wqa[DM];
__device__ __align__(16) float g_wka[DM];
__device__ __align__(16) float g_wewa[DE];
__device__ float g_cbias;
__device__ int   g_is64;

__device__ __align__(16) float g_qa[MAX_NODES];
__device__ __align__(16) float g_ka[MAX_NODES];
__device__ __align__(16) float g_attsum[MAX_NODES];
__device__ __align__(16) float g_alphasum[MAX_NODES];
__device__ __align__(16) float g_attexp[MAX_E];
__device__ __align__(16) float g_accx[(size_t)MAX_NODES * DM];
__device__ __align__(16) float g_acc64[(size_t)MAX_NODES * DE];

// sort structures
__device__ __align__(16) int  g_hist[MAX_NODES];
__device__ __align__(16) int  g_segstart[MAX_NODES];
__device__ __align__(16) int  g_cursor[MAX_NODES];
__device__ __align__(16) int  g_blocksum[1024];
__device__ __align__(16) int2 g_epair[MAX_E];          // {gsrc, gdst} cached by edge1
__device__ __align__(16) int4 g_sp[MAX_E];             // {gdst, e, alpha(bits), pad}

// ---------------- helpers ----------------
__device__ __forceinline__ void ffma2(ull& d, ull a, ull b) {
    asm("fma.rn.f32x2 %0, %1, %2, %3;" : "=l"(d) : "l"(a), "l"(b), "l"(d));
}
__device__ __forceinline__ float hadd2(ull v) {
    float lo = __uint_as_float((unsigned)(v & 0xffffffffull));
    float hi = __uint_as_float((unsigned)(v >> 32));
    return lo + hi;
}
__device__ __forceinline__ int ld_idx(const void* p, long long i, int is64) {
    if (is64) return (int)((const long long*)p)[i];
    return ((const int*)p)[i];
}

// ---------------- kernels ----------------

// merged: zero (blocks 0..gridDim-2) + prep + dtype-detect (last block)
__global__ void k_init(const float* __restrict__ Wq, const float* __restrict__ bq,
                       const float* __restrict__ Wk, const float* __restrict__ bk,
                       const float* __restrict__ Wew, const float* __restrict__ bew,
                       const float* __restrict__ Wa, const int* __restrict__ ei,
                       int nodes) {
    if (blockIdx.x == gridDim.x - 1) {
        int t = threadIdx.x;
        if (t < DM) {
            float s1 = 0.f, s2 = 0.f;
            for (int j = 0; j < DM; j++) {
                float w = Wa[j];
                s1 += Wq[t * DM + j] * w;
                s2 += Wk[t * DM + j] * w;
            }
            g_wqa[t] = s1;
            g_wka[t] = s2;
        } else if (t < DM + DE) {
            int r = t - DM;
            float s = 0.f;
            for (int c = 0; c < DM; c++) s += Wew[r * DM + c] * Wa[c];
            g_wewa[r] = s;
        } else if (t == DM + DE) {
            float s = 0.f;
            for (int j = 0; j < DM; j++) s += (bq[j] + bk[j] + bew[j]) * Wa[j];
            g_cbias = s;
        } else if (t == DM + DE + 1) {
            g_is64 = ((ei[1] | ei[3] | ei[5] | ei[7]) == 0) ? 1 : 0;
        }
    } else {
        int i = blockIdx.x * blockDim.x + threadIdx.x;
        int stride = (gridDim.x - 1) * blockDim.x;
        for (int j = i; j < nodes; j += stride) { g_attsum[j] = 0.f; g_hist[j] = 0; }
    }
}

// per-node scalars qa = x·wqa, ka = x·wka  (one warp per FOUR nodes -> MLP 4)
__global__ void k_qaka(const float* __restrict__ x, int nodes) {
    int w = (blockIdx.x * blockDim.x + threadIdx.x) >> 5;
    int lane = threadIdx.x & 31;
    int g0 = w * 4;
    if (g0 >= nodes) return;
    const float4* x4 = (const float4*)x;
    float4 wq = ((const float4*)g_wqa)[lane];
    float4 wk = ((const float4*)g_wka)[lane];
    float pq[4], pk[4];
    float4 a[4];
    #pragma unroll
    for (int j = 0; j < 4; j++) {
        int gi = (g0 + j < nodes) ? g0 + j : g0;
        a[j] = x4[(size_t)gi * 32 + lane];
    }
    #pragma unroll
    for (int j = 0; j < 4; j++) {
        pq[j] = a[j].x * wq.x + a[j].y * wq.y + a[j].z * wq.z + a[j].w * wq.w;
        pk[j] = a[j].x * wk.x + a[j].y * wk.y + a[j].z * wk.z + a[j].w * wk.w;
    }
    #pragma unroll
    for (int off = 16; off; off >>= 1) {
        #pragma unroll
        for (int j = 0; j < 4; j++) {
            pq[j] += __shfl_down_sync(0xffffffffu, pq[j], off);
            pk[j] += __shfl_down_sync(0xffffffffu, pk[j], off);
        }
    }
    if (lane == 0) {
        #pragma unroll
        for (int j = 0; j < 4; j++) {
            if (g0 + j < nodes) { g_qa[g0 + j] = pq[j]; g_ka[g0 + j] = pk[j]; }
        }
    }
}

// pass 1: per edge logit -> exp, denominator per gdst, histogram per gsrc,
// cache (gsrc,gdst). 8 lanes/edge.
__global__ void k_edge1(const void* __restrict__ ei, const float* __restrict__ emb,
                        const void* __restrict__ bi, int E, int Nn) {
    int gid = blockIdx.x * blockDim.x + threadIdx.x;
    int e = gid >> 3;
    int l = gid & 7;
    bool valid = e < E;
    int ec = valid ? e : 0;
    const float4* e4 = (const float4*)emb;
    float4 a = e4[(size_t)ec * 16 + l * 2];
    float4 b = e4[(size_t)ec * 16 + l * 2 + 1];
    float4 w1 = ((const float4*)g_wewa)[l * 2];
    float4 w2 = ((const float4*)g_wewa)[l * 2 + 1];
    float p = a.x * w1.x + a.y * w1.y + a.z * w1.z + a.w * w1.w
            + b.x * w2.x + b.y * w2.y + b.z * w2.z + b.w * w2.w;
    p += __shfl_down_sync(0xffffffffu, p, 4, 8);
    p += __shfl_down_sync(0xffffffffu, p, 2, 8);
    p += __shfl_down_sync(0xffffffffu, p, 1, 8);
    if (valid && l == 0) {
        int is64 = g_is64;
        int s  = ld_idx(ei, e, is64);
        int d  = ld_idx(ei, (long long)E + e, is64);
        int bb = ld_idx(bi, e, is64);
        int gsrc = bb * Nn + s;
        int gdst = bb * Nn + d;
        g_epair[e] = make_int2(gsrc, gdst);
        float logit = (g_qa[gsrc] + g_ka[gdst] + p + g_cbias) * 0.25f; // 1/sqrt(16)
        float ex = expf(logit);
        g_attexp[e] = ex;
        atomicAdd(&g_attsum[gdst], ex);
        atomicAdd(&g_hist[gsrc], 1);
    }
}

// ---- 3-step exclusive scan of g_hist ----
__global__ void k_scan1(int nodes) {
    __shared__ int s[256];
    int i = blockIdx.x * 256 + threadIdx.x;
    int v = (i < nodes) ? g_hist[i] : 0;
    s[threadIdx.x] = v;
    __syncthreads();
    #pragma unroll
    for (int off = 128; off; off >>= 1) {
        if (threadIdx.x < off) s[threadIdx.x] += s[threadIdx.x + off];
        __syncthreads();
    }
    if (threadIdx.x == 0) g_blocksum[blockIdx.x] = s[0];
}

__global__ void k_scan2(int nb) {
    __shared__ int s[1024];
    int t = threadIdx.x;
    int v = (t < nb) ? g_blocksum[t] : 0;
    s[t] = v;
    __syncthreads();
    #pragma unroll
    for (int off = 1; off < 1024; off <<= 1) {
        int add = (t >= off) ? s[t - off] : 0;
        __syncthreads();
        s[t] += add;
        __syncthreads();
    }
    if (t < nb) g_blocksum[t] = s[t] - v;   // exclusive
}

__global__ void k_scan3(int nodes) {
    __shared__ int s[256];
    int i = blockIdx.x * 256 + threadIdx.x;
    int v = (i < nodes) ? g_hist[i] : 0;
    s[threadIdx.x] = v;
    __syncthreads();
    #pragma unroll
    for (int off = 1; off < 256; off <<= 1) {
        int add = (threadIdx.x >= off) ? s[threadIdx.x - off] : 0;
        __syncthreads();
        s[threadIdx.x] += add;
        __syncthreads();
    }
    if (i < nodes) {
        int start = g_blocksum[blockIdx.x] + s[threadIdx.x] - v;
        g_segstart[i] = start;
        g_cursor[i]   = start;
    }
}

// scatter: per edge, compute alpha, place packed payload into gsrc-sorted slot
__global__ void k_scatter(int E) {
    int e = blockIdx.x * blockDim.x + threadIdx.x;
    if (e >= E) return;
    int2 pr = g_epair[e];
    float alpha = g_attexp[e] / (g_attsum[pr.y] + 1e-9f);
    int pos = atomicAdd(&g_cursor[pr.x], 1);
    g_sp[pos] = make_int4(pr.y, e, __float_as_int(alpha), 0);
}

// segmented accumulation: one warp per node, registers only, 4-wide MLP
__global__ void k_accum(const float* __restrict__ x, const float* __restrict__ emb,
                        int nodes) {
    int g = (blockIdx.x * blockDim.x + threadIdx.x) >> 5;
    int lane = threadIdx.x & 31;
    if (g >= nodes) return;
    int i   = g_segstart[g];
    int end = g_cursor[g];
    const float4* x4 = (const float4*)x;
    const float2* e2 = (const float2*)emb;
    float4 ax = make_float4(0.f, 0.f, 0.f, 0.f);
    float2 ae = make_float2(0.f, 0.f);
    float asum = 0.f;
    for (; i + 3 < end; i += 4) {
        int4 p0 = __ldg(&g_sp[i]);
        int4 p1 = __ldg(&g_sp[i + 1]);
        int4 p2 = __ldg(&g_sp[i + 2]);
        int4 p3 = __ldg(&g_sp[i + 3]);
        float a0 = __int_as_float(p0.z), a1 = __int_as_float(p1.z);
        float a2 = __int_as_float(p2.z), a3 = __int_as_float(p3.z);
        float4 xv0 = x4[(size_t)p0.x * 32 + lane];
        float4 xv1 = x4[(size_t)p1.x * 32 + lane];
        float4 xv2 = x4[(size_t)p2.x * 32 + lane];
        float4 xv3 = x4[(size_t)p3.x * 32 + lane];
        float2 ev0 = e2[(size_t)p0.y * 32 + lane];
        float2 ev1 = e2[(size_t)p1.y * 32 + lane];
        float2 ev2 = e2[(size_t)p2.y * 32 + lane];
        float2 ev3 = e2[(size_t)p3.y * 32 + lane];
        ax.x += a0 * xv0.x + a1 * xv1.x + a2 * xv2.x + a3 * xv3.x;
        ax.y += a0 * xv0.y + a1 * xv1.y + a2 * xv2.y + a3 * xv3.y;
        ax.z += a0 * xv0.z + a1 * xv1.z + a2 * xv2.z + a3 * xv3.z;
        ax.w += a0 * xv0.w + a1 * xv1.w + a2 * xv2.w + a3 * xv3.w;
        ae.x += a0 * ev0.x + a1 * ev1.x + a2 * ev2.x + a3 * ev3.x;
        ae.y += a0 * ev0.y + a1 * ev1.y + a2 * ev2.y + a3 * ev3.y;
        asum += (a0 + a1) + (a2 + a3);
    }
    for (; i + 1 < end; i += 2) {
        int4 p0 = __ldg(&g_sp[i]);
        int4 p1 = __ldg(&g_sp[i + 1]);
        float a0 = __int_as_float(p0.z), a1 = __int_as_float(p1.z);
        float4 xv0 = x4[(size_t)p0.x * 32 + lane];
        float4 xv1 = x4[(size_t)p1.x * 32 + lane];
        float2 ev0 = e2[(size_t)p0.y * 32 + lane];
        float2 ev1 = e2[(size_t)p1.y * 32 + lane];
        ax.x += a0 * xv0.x + a1 * xv1.x;
        ax.y += a0 * xv0.y + a1 * xv1.y;
        ax.z += a0 * xv0.z + a1 * xv1.z;
        ax.w += a0 * xv0.w + a1 * xv1.w;
        ae.x += a0 * ev0.x + a1 * ev1.x;
        ae.y += a0 * ev0.y + a1 * ev1.y;
        asum += a0 + a1;
    }
    if (i < end) {
        int4 p = __ldg(&g_sp[i]);
        float a = __int_as_float(p.z);
        float4 xv = x4[(size_t)p.x * 32 + lane];
        float2 ev = e2[(size_t)p.y * 32 + lane];
        ax.x += a * xv.x; ax.y += a * xv.y; ax.z += a * xv.z; ax.w += a * xv.w;
        ae.x += a * ev.x; ae.y += a * ev.y;
        asum += a;
    }
    ((float4*)g_accx)[(size_t)g * 32 + lane] = ax;
    ((float2*)g_acc64)[(size_t)g * 32 + lane] = ae;
    if (lane == 0) g_alphasum[g] = asum;
}

// PERSISTENT GEMM v5: 148 blocks x 256 threads, BM=64, per-thread 8 rows x 4 cols.
// sW: [96 k2][256 floats] pair-interleaved (f = 2c+h) with XOR-16B swizzle
//     (f_phys = f ^ 4 when (f>>5)&1) -> both W LDS.128s conflict-free.
// sA: k2-major pair-packed [96 k2][64 rows * 2] -> 4 LDS.128 BROADCASTS per k2
//     deliver all 8 row k-pairs (1 cyc each).
#define SW_K2 96
#define KOUT_BLOCKS 148

__global__ void __launch_bounds__(256)
k_out(const float* __restrict__ Wv, const float* __restrict__ bv,
      const float* __restrict__ Wev, const float* __restrict__ bev,
      float* __restrict__ out, int nodes) {
    extern __shared__ float smem[];
    float* sW = smem;                    // 96 * 256 floats (96 KB)
    float* sA = smem + SW_K2 * 256;      // 96 * 128 floats (48 KB)

    int tid = threadIdx.x;
    int tx  = tid & 31;      // cols 4tx .. 4tx+3
    int ty  = tid >> 5;      // rows ty*8 .. ty*8+7
    int wb  = (tx >> 2) & 1; // swizzle bit for this thread's W window

    // ---- load full W once (swizzled): 6144 float4, 24 per thread ----
    #pragma unroll
    for (int t = 0; t < 24; t++) {
        int i4 = tid + t * 256;          // 0..6143
        int k  = i4 >> 5;                // W row 0..191
        int c4 = (i4 & 31) << 2;         // col 0,4,...,124
        float4 v = (k < 128) ? *(const float4*)&Wv[k * DM + c4]
                             : *(const float4*)&Wev[(k - 128) * DM + c4];
        float* row = &sW[(k >> 1) * 256];
        int h = k & 1;
        #pragma unroll
        for (int j = 0; j < 4; j++) {
            int f = ((c4 + j) << 1) | h;
            int fp = f ^ (((f >> 5) & 1) << 2);
            row[fp] = (&v.x)[j];
        }
    }

    float4 b1 = *(const float4*)&bv[tx * 4];
    float4 b2 = *(const float4*)&bev[tx * 4];
    float4 bs = make_float4(b1.x + b2.x, b1.y + b2.y, b1.z + b2.z, b1.w + b2.w);

    int ntiles = (nodes + 63) >> 6;
    for (int tile = blockIdx.x; tile < ntiles; tile += KOUT_BLOCKS) {
        int g0 = tile << 6;
        __syncthreads();   // W ready (first iter) / prior tile compute done

        // ---- fill sA k2-major: lane = row, iterate k. 12 iters/thread ----
        // thread handles row m = tid & 63, k-quads kq = ((tid>>6) + 4t)*4
        {
            int m = tid & 63;
            int gm = g0 + m; if (gm >= nodes) gm = nodes - 1;
            const float* arow = &g_accx[(size_t)gm * DM];
            const float* erow = &g_acc64[(size_t)gm * DE];
            int kq0 = (tid >> 6) << 2;       // 0,4,8,12
            #pragma unroll
            for (int t = 0; t < 12; t++) {
                int kq = kq0 + t * 16;       // step 16 floats
                float4 v = (kq < 128) ? *(const float4*)&arow[kq]
                                      : *(const float4*)&erow[kq - 128];
                int k2 = kq >> 1;            // first k-pair row
                *(float2*)&sA[(k2 + 0) * 128 + m * 2] = make_float2(v.x, v.y);
                *(float2*)&sA[(k2 + 1) * 128 + m * 2] = make_float2(v.z, v.w);
            }
        }
        __syncthreads();

        // ---- compute: 96 k2 steps, 8 rows x 4 cols, all FFMA2 ----
        ull acc[8][4];
        #pragma unroll
        for (int i = 0; i < 8; i++)
            #pragma unroll
            for (int j = 0; j < 4; j++) acc[i][j] = 0ull;

        #pragma unroll 4
        for (int k2 = 0; k2 < SW_K2; k2++) {
            const float* aRow = &sA[k2 * 128 + ty * 16];   // 8 rows * 2 floats
            ulonglong2 q0 = *(const ulonglong2*)&aRow[0];   // rows 0,1 (broadcast)
            ulonglong2 q1 = *(const ulonglong2*)&aRow[4];   // rows 2,3
            ulonglong2 q2 = *(const ulonglong2*)&aRow[8];   // rows 4,5
            ulonglong2 q3 = *(const ulonglong2*)&aRow[12];  // rows 6,7
            const float* wRow = &sW[k2 * 256];
            ulonglong2 p0 = *(const ulonglong2*)&wRow[tx * 8 + (wb << 2)];       // w0,w1
            ulonglong2 p1 = *(const ulonglong2*)&wRow[tx * 8 + ((1 - wb) << 2)]; // w2,w3
            ull a2[8] = { q0.x, q0.y, q1.x, q1.y, q2.x, q2.y, q3.x, q3.y };
            #pragma unroll
            for (int i = 0; i < 8; i++) {
                ffma2(acc[i][0], a2[i], p0.x);
                ffma2(acc[i][1], a2[i], p0.y);
                ffma2(acc[i][2], a2[i], p1.x);
                ffma2(acc[i][3], a2[i], p1.y);
            }
        }

        // ---- epilogue ----
        #pragma unroll
        for (int i = 0; i < 8; i++) {
            int g = g0 + ty * 8 + i;
            if (g < nodes) {
                float as = g_alphasum[g];
                float4 o;
                o.x = hadd2(acc[i][0]) + as * bs.x;
                o.y = hadd2(acc[i][1]) + as * bs.y;
                o.z = hadd2(acc[i][2]) + as * bs.z;
                o.w = hadd2(acc[i][3]) + as * bs.w;
                *(float4*)&out[(size_t)g * DM + tx * 4] = o;
            }
        }
    }
}

// ---------------- launcher ----------------
extern "C" void kernel_launch(void* const* d_in, const int* in_sizes, int n_in,
                              void* d_out, int out_size) {
    const float* x   = (const float*)d_in[0];
    const void*  ei  = d_in[1];
    const float* emb = (const float*)d_in[2];
    const void*  bi  = d_in[3];
    int base = 4;
    if (n_in >= 16 && in_sizes[4] <= 2) base = 5;
    const float* Wq  = (const float*)d_in[base + 0];
    const float* bq  = (const float*)d_in[base + 1];
    const float* Wk  = (const float*)d_in[base + 2];
    const float* bk  = (const float*)d_in[base + 3];
    const float* Wv  = (const float*)d_in[base + 4];
    const float* bv  = (const float*)d_in[base + 5];
    const float* Wew = (const float*)d_in[base + 6];
    const float* bew = (const float*)d_in[base + 7];
    const float* Wev = (const float*)d_in[base + 8];
    const float* bev = (const float*)d_in[base + 9];
    const float* Wa  = (const float*)d_in[base + 10];

    int nodes = in_sizes[0] / DM;   // B*N
    int E     = in_sizes[3];
    int Nn    = nodes / 4;          // N (B = 4)
    int nb    = (nodes + 255) / 256;

    // smem: 96*256 (sW) + 96*128 (sA) floats = 36864 floats = 147456 B
    int smem_bytes = (SW_K2 * 256 + SW_K2 * 128) * (int)sizeof(float);
    cudaFuncSetAttribute(k_out, cudaFuncAttributeMaxDynamicSharedMemorySize, smem_bytes);

    k_init<<<257, 256>>>(Wq, bq, Wk, bk, Wew, bew, Wa, (const int*)ei, nodes);
    k_qaka<<<(nodes / 4 + 7) / 8, 256>>>(x, nodes);
    k_edge1<<<(E + 31) / 32, 256>>>(ei, emb, bi, E, Nn);
    k_scan1<<<nb, 256>>>(nodes);
    k_scan2<<<1, 1024>>>(nb);
    k_scan3<<<nb, 256>>>(nodes);
    k_scatter<<<(E + 255) / 256, 256>>>(E);
    k_accum<<<(nodes + 7) / 8, 256>>>(x, emb, nodes);
    k_out<<<KOUT_BLOCKS, 256, smem_bytes>>>(Wv, bv, Wev, bev, (float*)d_out, nodes);
}